// round 14
// baseline (speedup 1.0000x reference)
#include <cuda_runtime.h>
#include <cuda_fp16.h>

#define S_LEN 4096
#define TWO_PI_F 6.28318530717958647692f

typedef unsigned long long u64;

// fp32 char_P [j][i] + rpV table; quad-packed fp16 weights:
// uint4 index (q*64 + i2): component jj = half2( W[2*i2][4q+jj], W[2*i2+1][4q+jj] )
__device__ float  g_cPt[64 * 64];
__device__ float  g_rpVt[64 * 64];     // [j][i] = 1/(i*64+j+2)
__device__ uint4  g_M1q[16 * 64];
__device__ uint4  g_R1q[16 * 64];
__device__ uint4  g_M2q[32 * 64];
__device__ uint4  g_P1q[32 * 64];
__device__ uint4  g_P2q[32 * 64];
// rp for phi build: per (q,i2): 2 float4 = (rp(i0,j0),rp(i1,j0),rp(i0,j1),rp(i1,j1)),(... j2,j3)
__device__ float4 g_rpQ[2048 * 2];

__device__ __forceinline__ unsigned packh2(float lo, float hi)
{
    __half2 h = __floats2half2_rn(lo, hi);
    return *(unsigned*)&h;
}

__global__ void prep_kernel(
    const float* __restrict__ cP, const float* __restrict__ M1,
    const float* __restrict__ R1, const float* __restrict__ M2,
    const float* __restrict__ P1, const float* __restrict__ P2)
{
    int t = blockIdx.x * blockDim.x + threadIdx.x;
    if (t < 2048) {                       // D-size matrices: q<32, i2<64
        int q = t >> 6, i2l = t & 63;
        int i0 = 2 * i2l, i1 = i0 + 1;
        uint4 m2, p1, p2; float4 ra, rb;
        int j0 = 4 * q;
        m2.x = packh2(M2[i0*128 + j0+0], M2[i1*128 + j0+0]);
        m2.y = packh2(M2[i0*128 + j0+1], M2[i1*128 + j0+1]);
        m2.z = packh2(M2[i0*128 + j0+2], M2[i1*128 + j0+2]);
        m2.w = packh2(M2[i0*128 + j0+3], M2[i1*128 + j0+3]);
        p1.x = packh2(P1[i0*128 + j0+0], P1[i1*128 + j0+0]);
        p1.y = packh2(P1[i0*128 + j0+1], P1[i1*128 + j0+1]);
        p1.z = packh2(P1[i0*128 + j0+2], P1[i1*128 + j0+2]);
        p1.w = packh2(P1[i0*128 + j0+3], P1[i1*128 + j0+3]);
        p2.x = packh2(P2[i0*128 + j0+0], P2[i1*128 + j0+0]);
        p2.y = packh2(P2[i0*128 + j0+1], P2[i1*128 + j0+1]);
        p2.z = packh2(P2[i0*128 + j0+2], P2[i1*128 + j0+2]);
        p2.w = packh2(P2[i0*128 + j0+3], P2[i1*128 + j0+3]);
        g_M2q[t] = m2; g_P1q[t] = p1; g_P2q[t] = p2;
        ra.x = 1.0f / (float)(i0*128 + j0+0 + 2);
        ra.y = 1.0f / (float)(i1*128 + j0+0 + 2);
        ra.z = 1.0f / (float)(i0*128 + j0+1 + 2);
        ra.w = 1.0f / (float)(i1*128 + j0+1 + 2);
        rb.x = 1.0f / (float)(i0*128 + j0+2 + 2);
        rb.y = 1.0f / (float)(i1*128 + j0+2 + 2);
        rb.z = 1.0f / (float)(i0*128 + j0+3 + 2);
        rb.w = 1.0f / (float)(i1*128 + j0+3 + 2);
        g_rpQ[2*t] = ra; g_rpQ[2*t+1] = rb;
    }
    if (t < 1024) {                       // V->D matrices: q<16, i2<64
        int q = t >> 6, i2l = t & 63;
        int i0 = 2 * i2l, i1 = i0 + 1;
        int j0 = 4 * q;
        uint4 m1, r1;
        m1.x = packh2(M1[i0*64 + j0+0], M1[i1*64 + j0+0]);
        m1.y = packh2(M1[i0*64 + j0+1], M1[i1*64 + j0+1]);
        m1.z = packh2(M1[i0*64 + j0+2], M1[i1*64 + j0+2]);
        m1.w = packh2(M1[i0*64 + j0+3], M1[i1*64 + j0+3]);
        r1.x = packh2(R1[i0*64 + j0+0], R1[i1*64 + j0+0]);
        r1.y = packh2(R1[i0*64 + j0+1], R1[i1*64 + j0+1]);
        r1.z = packh2(R1[i0*64 + j0+2], R1[i1*64 + j0+2]);
        r1.w = packh2(R1[i0*64 + j0+3], R1[i1*64 + j0+3]);
        g_M1q[t] = m1; g_R1q[t] = r1;
    }
    if (t < 4096) {
        int i = t >> 6, j = t & 63;
        g_cPt[j * 64 + i] = cP[t];
        g_rpVt[t] = 1.0f / (float)((t & 63) * 64 + (t >> 6) + 2);
    }
}

// cos(2*pi*s/p) via table rp; exact-frac with fma, __cosf on [-pi,pi]
__device__ __forceinline__ float pcos(float sf, float rp)
{
    float f = sf * rp;
    float n = rintf(f);
    float r = fmaf(sf, rp, -n);
    return __cosf(TWO_PI_F * r);
}

// ---- packed f32x2 helpers; payload in u64 ----
__device__ __forceinline__ u64 fma2(u64 a, u64 b, u64 c)
{ u64 d; asm("fma.rn.f32x2 %0, %1, %2, %3;" : "=l"(d) : "l"(a), "l"(b), "l"(c)); return d; }
__device__ __forceinline__ u64 mul2(u64 a, u64 b)
{ u64 d; asm("mul.rn.f32x2 %0, %1, %2;" : "=l"(d) : "l"(a), "l"(b)); return d; }
__device__ __forceinline__ u64 add2(u64 a, u64 b)
{ u64 d; asm("add.rn.f32x2 %0, %1, %2;" : "=l"(d) : "l"(a), "l"(b)); return d; }
__device__ __forceinline__ u64 bcast2(float x)
{ u64 d; asm("mov.b64 %0, {%1, %1};" : "=l"(d) : "f"(x)); return d; }
__device__ __forceinline__ u64 f2d(float x, float y)
{ u64 d; asm("mov.b64 %0, {%1, %2};" : "=l"(d) : "f"(x), "f"(y)); return d; }
__device__ __forceinline__ float2 d2f(u64 d)
{ float2 v; asm("mov.b64 {%0, %1}, %2;" : "=f"(v.x), "=f"(v.y) : "l"(d)); return v; }

// smem layout (float units)
#define OFF_PHI  0          // 2048 uint4 = 8192 floats
#define OFF_PART 8192       // 2048 u64 = 4096 floats
#define OFF_XST  12288      // 256
#define OFF_HST  12544      // 256
#define OFF_LN1  12800      // 512
#define OFF_H1S  13312      // 512
#define OFF_LN2  13824      // 512
#define OFF_WSMU 14336      // 16 u64 = 32 floats
#define OFF_WSQU 14368      // 32
#define SM_FLOATS 14400
#define SMEM_BYTES (SM_FLOATS * 4)

// acc layout: A00=(i0,b01) A01=(i0,b23) A10=(i1,b01) A11=(i1,b23)
#define DECL_ACC u64 A00 = 0, A01 = 0, A10 = 0, A11 = 0;

#define WJ(CP, JJ, ACT, Q) {                                            \
    float2 wf = __half22float2(*(const __half2*)&(CP));                 \
    ulonglong2 a = *(const ulonglong2*)&(ACT)[(((Q)*4+(JJ)))*4];        \
    u64 w0 = bcast2(wf.x), w1 = bcast2(wf.y);                           \
    A00 = fma2(w0, a.x, A00); A01 = fma2(w0, a.y, A01);                 \
    A10 = fma2(w1, a.x, A10); A11 = fma2(w1, a.y, A11); }

#define WQUAD(WQ, ACT, Q) {                                             \
    uint4 wq = WQ[(Q)*64 + i2];                                         \
    WJ(wq.x, 0, ACT, Q); WJ(wq.y, 1, ACT, Q);                           \
    WJ(wq.z, 2, ACT, Q); WJ(wq.w, 3, ACT, Q); }

#define PJ(WC, PC, JJ, ACT, Q) {                                        \
    __half2 wp = __hmul2(*(const __half2*)&(WC), *(const __half2*)&(PC)); \
    float2 wf = __half22float2(wp);                                     \
    ulonglong2 a = *(const ulonglong2*)&(ACT)[(((Q)*4+(JJ)))*4];        \
    u64 w0 = bcast2(wf.x), w1 = bcast2(wf.y);                           \
    A00 = fma2(w0, a.x, A00); A01 = fma2(w0, a.y, A01);                 \
    A10 = fma2(w1, a.x, A10); A11 = fma2(w1, a.y, A11); }

#define PQUAD(WQ, ACT, Q) {                                             \
    uint4 wq = WQ[(Q)*64 + i2];                                         \
    uint4 pq = phiQ[(Q)*64 + i2];                                       \
    PJ(wq.x, pq.x, 0, ACT, Q); PJ(wq.y, pq.y, 1, ACT, Q);               \
    PJ(wq.z, pq.z, 2, ACT, Q); PJ(wq.w, pq.w, 3, ACT, Q); }

// partials: [slice][i*2 + bp] u64  (i = 2*i2 (+1), bp: 0=(b0,b1) 1=(b2,b3))
#define STOREP() {                                                      \
    ulonglong2 s0; s0.x = A00; s0.y = A01;                              \
    *(ulonglong2*)&partd[js8 * 256 + i2 * 4 + 0] = s0;                  \
    ulonglong2 s1; s1.x = A10; s1.y = A11;                              \
    *(ulonglong2*)&partd[js8 * 256 + i2 * 4 + 2] = s1; }

__global__ __launch_bounds__(512, 2)
void hier_kernel(const int*   __restrict__ tokens,
                 const int*   __restrict__ positions,
                 const float* __restrict__ emb,
                 const float* __restrict__ g1, const float* __restrict__ b1,
                 const float* __restrict__ g2, const float* __restrict__ b2,
                 float*       __restrict__ out)
{
    extern __shared__ __align__(16) float sm[];
    uint4* phiQ = (uint4*)(sm + OFF_PHI);       // quad-packed fp16 phi
    u64*   partd = (u64*)(sm + OFF_PART);
    float* xsT   = sm + OFF_XST;                // [j][4b]
    float* hsT   = sm + OFF_HST;
    float* ln1T  = sm + OFF_LN1;
    float* h1sT  = sm + OFF_H1S;
    float* ln2T  = sm + OFF_LN2;
    u64*   wsmU  = (u64*)(sm + OFF_WSMU);
    u64*   wsqU  = (u64*)(sm + OFF_WSQU);

    const int tid = threadIdx.x;
    const int s   = blockIdx.x;
    const float sf = (float)positions[s];

    // ---- build quad-packed fp16 phiD ----
    {
        const int bi2 = tid & 63, bqg = tid >> 6;
#pragma unroll
        for (int m = 0; m < 4; ++m) {
            int q = bqg * 4 + m;
            int t2 = q * 64 + bi2;
            float4 rA = g_rpQ[2 * t2];
            float4 rB = g_rpQ[2 * t2 + 1];
            uint4 pk;
            pk.x = packh2(pcos(sf, rA.x), pcos(sf, rA.y));
            pk.y = packh2(pcos(sf, rA.z), pcos(sf, rA.w));
            pk.z = packh2(pcos(sf, rB.x), pcos(sf, rB.y));
            pk.w = packh2(pcos(sf, rB.z), pcos(sf, rB.w));
            phiQ[t2] = pk;
        }
    }

    // ---- gather embeddings: xsT[j][b] ----
    if (tid < 256) {
        int b0 = tid >> 6, j0 = tid & 63;
        int tok = tokens[b0 * S_LEN + s];
        xsT[j0 * 4 + b0] = emb[tok * 64 + j0];
    }
    __syncthreads();

    // =====================================================================
    // Layer 0 (V=64): 64 i x 8 j-slices of 8, f32x2 over batch pairs
    // =====================================================================
    {
        const int i = tid & 63, sl = tid >> 6;
        u64 a01 = 0, a23 = 0;
#pragma unroll
        for (int jj = 0; jj < 8; ++jj) {
            int j = sl * 8 + jj;
            float pw = g_cPt[j * 64 + i] * pcos(sf, g_rpVt[j * 64 + i]);
            u64 p2 = bcast2(pw);
            ulonglong2 ad = *(const ulonglong2*)&xsT[j * 4];
            a01 = fma2(p2, ad.x, a01);
            a23 = fma2(p2, ad.y, a23);
        }
        ulonglong2 st; st.x = a01; st.y = a23;
        *(ulonglong2*)&partd[sl * 128 + i * 2] = st;
    }
    __syncthreads();
    if (tid < 128) {
        u64 v = 0;
#pragma unroll
        for (int sl = 0; sl < 8; ++sl) v = add2(v, partd[sl * 128 + tid]);
        *(u64*)&hsT[tid * 2] = v;   // hsT[i][4b]: (i = tid>>1, bp = tid&1)
    }
    __syncthreads();

    // D-stage mapping: warp = (i-half, j-slice); lane carries i-pair
    const int w    = tid >> 5;
    const int ih   = w & 1;
    const int js8  = w >> 1;                 // 0..7
    const int i2   = ih * 32 + (tid & 31);   // i-pair 0..63
    // reduce/LN mapping (tid < 256): i = tid>>1, bp = tid&1
    const int ii   = tid >> 1;
    const int bp   = tid & 1;

    // =====================================================================
    // t1 = M1 @ h : quads js8*2, js8*2+1
    // =====================================================================
    {
        DECL_ACC;
        WQUAD(g_M1q, hsT, js8 * 2 + 0);
        WQUAD(g_M1q, hsT, js8 * 2 + 1);
        STOREP();
    }
    __syncthreads();

    // ---- reduce t1 + LayerNorm 1 ----
    if (tid < 256) {
        u64 v = 0;
#pragma unroll
        for (int sl = 0; sl < 8; ++sl) v = add2(v, partd[sl * 256 + tid]);
        u64 sv = v, sq = mul2(v, v);
#pragma unroll
        for (int o = 2; o <= 16; o <<= 1) {
            sv = add2(sv, __shfl_xor_sync(0xffffffffu, sv, o));
            sq = add2(sq, __shfl_xor_sync(0xffffffffu, sq, o));
        }
        int lane = tid & 31, wid = tid >> 5;
        if (lane < 2) { wsmU[wid * 2 + lane] = sv; wsqU[wid * 2 + lane] = sq; }
        partd[1792 + tid] = v;  // stash (slice 7 already consumed)
    }
    __syncthreads();
    if (tid < 256) {
        u64 smS = wsmU[bp], sqS = wsqU[bp];
#pragma unroll
        for (int k = 1; k < 8; ++k) {
            smS = add2(smS, wsmU[k * 2 + bp]);
            sqS = add2(sqS, wsqU[k * 2 + bp]);
        }
        u64 mean2 = mul2(smS, bcast2(0.0078125f));
        u64 ex2   = mul2(sqS, bcast2(0.0078125f));
        u64 var2  = fma2(mean2, mul2(mean2, bcast2(-1.f)), ex2);
        float2 vf = d2f(add2(var2, bcast2(1e-5f)));
        u64 rstd2 = f2d(rsqrtf(vf.x), rsqrtf(vf.y));
        u64 vv  = partd[1792 + tid];
        u64 cen = fma2(mean2, bcast2(-1.f), vv);
        *(u64*)&ln1T[ii * 4 + bp * 2] =
            fma2(bcast2(g1[ii]), mul2(cen, rstd2), bcast2(b1[ii]));
    }
    __syncthreads();

    // =====================================================================
    // h1 = posnk(ln1, P1, phi) + R1 @ h : quads js8*4..+3 (P) + js8*2..+1 (R)
    // =====================================================================
    {
        DECL_ACC;
        PQUAD(g_P1q, ln1T, js8 * 4 + 0); PQUAD(g_P1q, ln1T, js8 * 4 + 1);
        PQUAD(g_P1q, ln1T, js8 * 4 + 2); PQUAD(g_P1q, ln1T, js8 * 4 + 3);
        WQUAD(g_R1q, hsT, js8 * 2 + 0);  WQUAD(g_R1q, hsT, js8 * 2 + 1);
        STOREP();
    }
    __syncthreads();
    if (tid < 256) {
        u64 v = 0;
#pragma unroll
        for (int sl = 0; sl < 8; ++sl) v = add2(v, partd[sl * 256 + tid]);
        *(u64*)&h1sT[tid * 2] = v;
    }
    __syncthreads();

    // =====================================================================
    // t2 = M2 @ h1 : quads js8*4..+3
    // =====================================================================
    {
        DECL_ACC;
        WQUAD(g_M2q, h1sT, js8 * 4 + 0); WQUAD(g_M2q, h1sT, js8 * 4 + 1);
        WQUAD(g_M2q, h1sT, js8 * 4 + 2); WQUAD(g_M2q, h1sT, js8 * 4 + 3);
        STOREP();
    }
    __syncthreads();

    // ---- reduce t2 + LayerNorm 2 (t2d kept in register for residual) ----
    u64 t2d = 0;
    if (tid < 256) {
#pragma unroll
        for (int sl = 0; sl < 8; ++sl) t2d = add2(t2d, partd[sl * 256 + tid]);
        u64 sv = t2d, sq = mul2(t2d, t2d);
#pragma unroll
        for (int o = 2; o <= 16; o <<= 1) {
            sv = add2(sv, __shfl_xor_sync(0xffffffffu, sv, o));
            sq = add2(sq, __shfl_xor_sync(0xffffffffu, sq, o));
        }
        int lane = tid & 31, wid = tid >> 5;
        if (lane < 2) { wsmU[wid * 2 + lane] = sv; wsqU[wid * 2 + lane] = sq; }
    }
    __syncthreads();
    if (tid < 256) {
        u64 smS = wsmU[bp], sqS = wsqU[bp];
#pragma unroll
        for (int k = 1; k < 8; ++k) {
            smS = add2(smS, wsmU[k * 2 + bp]);
            sqS = add2(sqS, wsqU[k * 2 + bp]);
        }
        u64 mean2 = mul2(smS, bcast2(0.0078125f));
        u64 ex2   = mul2(sqS, bcast2(0.0078125f));
        u64 var2  = fma2(mean2, mul2(mean2, bcast2(-1.f)), ex2);
        float2 vf = d2f(add2(var2, bcast2(1e-5f)));
        u64 rstd2 = f2d(rsqrtf(vf.x), rsqrtf(vf.y));
        u64 cen = fma2(mean2, bcast2(-1.f), t2d);
        *(u64*)&ln2T[ii * 4 + bp * 2] =
            fma2(bcast2(g2[ii]), mul2(cen, rstd2), bcast2(b2[ii]));
    }
    __syncthreads();

    // =====================================================================
    // out = posnk(ln2, P2, phi) + t2
    // =====================================================================
    {
        DECL_ACC;
        PQUAD(g_P2q, ln2T, js8 * 4 + 0); PQUAD(g_P2q, ln2T, js8 * 4 + 1);
        PQUAD(g_P2q, ln2T, js8 * 4 + 2); PQUAD(g_P2q, ln2T, js8 * 4 + 3);
        STOREP();
    }
    __syncthreads();
    if (tid < 256) {
        u64 v = t2d;
#pragma unroll
        for (int sl = 0; sl < 8; ++sl) v = add2(v, partd[sl * 256 + tid]);
        float2 f = d2f(v);
        int bA = bp * 2;
        out[((size_t)bA       * S_LEN + s) * 128 + ii] = f.x;
        out[((size_t)(bA + 1) * S_LEN + s) * 128 + ii] = f.y;
    }
}

extern "C" void kernel_launch(void* const* d_in, const int* in_sizes, int n_in,
                              void* d_out, int out_size)
{
    const int*   tokens    = (const int*)  d_in[0];
    const int*   positions = (const int*)  d_in[1];
    const float* emb       = (const float*)d_in[2];
    const float* char_P    = (const float*)d_in[3];
    const float* M1        = (const float*)d_in[4];
    const float* P1        = (const float*)d_in[5];
    const float* g1        = (const float*)d_in[6];
    const float* b1        = (const float*)d_in[7];
    const float* R1        = (const float*)d_in[8];
    const float* M2        = (const float*)d_in[9];
    const float* P2        = (const float*)d_in[10];
    const float* g2        = (const float*)d_in[11];
    const float* b2        = (const float*)d_in[12];
    float* out = (float*)d_out;

    cudaFuncSetAttribute(hier_kernel,
                         cudaFuncAttributeMaxDynamicSharedMemorySize, SMEM_BYTES);

    prep_kernel<<<32, 512>>>(char_P, M1, R1, M2, P1, P2);
    hier_kernel<<<S_LEN, 512, SMEM_BYTES>>>(tokens, positions, emb,
                                            g1, b1, g2, b2, out);
}

// round 15
// speedup vs baseline: 1.7152x; 1.7152x over previous
#include <cuda_runtime.h>
#include <cuda_fp16.h>

#define S_LEN 4096
#define TWO_PI_F 6.28318530717958647692f

typedef unsigned long long u64;

// Pair-packed fp16 weights: index (jp*64 + i2), jp = j/2, i2 = i-pair.
//   .x = half2( W[2i2][2jp],   W[2i2+1][2jp]   )
//   .y = half2( W[2i2][2jp+1], W[2i2+1][2jp+1] )
__device__ float  g_cPt[64 * 64];     // fp32 [j][i]
__device__ float  g_rpVt[64 * 64];    // [j][i] = 1/(i*64+j+2)
__device__ uint2  g_M1p[32 * 64];
__device__ uint2  g_R1p[32 * 64];
__device__ uint2  g_M2p[64 * 64];
__device__ uint2  g_P1p[64 * 64];
__device__ uint2  g_P2p[64 * 64];
// build rp: per (jp,i2): ( rp(i0,j), rp(i1,j), rp(i0,j+1), rp(i1,j+1) )
__device__ float4 g_rpP[64 * 64];

__device__ __forceinline__ unsigned packh2(float lo, float hi)
{
    __half2 h = __floats2half2_rn(lo, hi);
    return *(unsigned*)&h;
}

__global__ void prep_kernel(
    const float* __restrict__ cP, const float* __restrict__ M1,
    const float* __restrict__ R1, const float* __restrict__ M2,
    const float* __restrict__ P1, const float* __restrict__ P2)
{
    int t = blockIdx.x * blockDim.x + threadIdx.x;
    if (t < 4096) {                       // D mats: jp<64, i2<64
        int jp = t >> 6, i2l = t & 63;
        int j = 2 * jp, i0 = 2 * i2l, i1 = i0 + 1;
        uint2 v;
        v.x = packh2(M2[i0*128 + j],     M2[i1*128 + j]);
        v.y = packh2(M2[i0*128 + j + 1], M2[i1*128 + j + 1]);
        g_M2p[t] = v;
        v.x = packh2(P1[i0*128 + j],     P1[i1*128 + j]);
        v.y = packh2(P1[i0*128 + j + 1], P1[i1*128 + j + 1]);
        g_P1p[t] = v;
        v.x = packh2(P2[i0*128 + j],     P2[i1*128 + j]);
        v.y = packh2(P2[i0*128 + j + 1], P2[i1*128 + j + 1]);
        g_P2p[t] = v;
        float4 r;
        r.x = 1.0f / (float)(i0*128 + j + 2);
        r.y = 1.0f / (float)(i1*128 + j + 2);
        r.z = 1.0f / (float)(i0*128 + j + 3);
        r.w = 1.0f / (float)(i1*128 + j + 3);
        g_rpP[t] = r;
    }
    if (t < 2048) {                       // V mats: jp<32, i2<64
        int jp = t >> 6, i2l = t & 63;
        int j = 2 * jp, i0 = 2 * i2l, i1 = i0 + 1;
        uint2 v;
        v.x = packh2(M1[i0*64 + j],     M1[i1*64 + j]);
        v.y = packh2(M1[i0*64 + j + 1], M1[i1*64 + j + 1]);
        g_M1p[t] = v;
        v.x = packh2(R1[i0*64 + j],     R1[i1*64 + j]);
        v.y = packh2(R1[i0*64 + j + 1], R1[i1*64 + j + 1]);
        g_R1p[t] = v;
    }
    if (t < 4096) {
        int i = t >> 6, j = t & 63;
        g_cPt[j * 64 + i] = cP[t];
        g_rpVt[t] = 1.0f / (float)((t & 63) * 64 + (t >> 6) + 2);
    }
}

__device__ __forceinline__ float pcos(float sf, float rp)
{
    float f = sf * rp;
    float n = rintf(f);
    float r = fmaf(sf, rp, -n);
    return __cosf(TWO_PI_F * r);
}

// ---- packed f32x2 helpers; payload in u64 ----
__device__ __forceinline__ u64 fma2(u64 a, u64 b, u64 c)
{ u64 d; asm("fma.rn.f32x2 %0, %1, %2, %3;" : "=l"(d) : "l"(a), "l"(b), "l"(c)); return d; }
__device__ __forceinline__ u64 mul2(u64 a, u64 b)
{ u64 d; asm("mul.rn.f32x2 %0, %1, %2;" : "=l"(d) : "l"(a), "l"(b)); return d; }
__device__ __forceinline__ u64 add2(u64 a, u64 b)
{ u64 d; asm("add.rn.f32x2 %0, %1, %2;" : "=l"(d) : "l"(a), "l"(b)); return d; }
__device__ __forceinline__ u64 bcast2(float x)
{ u64 d; asm("mov.b64 %0, {%1, %1};" : "=l"(d) : "f"(x)); return d; }
__device__ __forceinline__ u64 f2d(float x, float y)
{ u64 d; asm("mov.b64 %0, {%1, %2};" : "=l"(d) : "f"(x), "f"(y)); return d; }
__device__ __forceinline__ float2 d2f(u64 d)
{ float2 v; asm("mov.b64 {%0, %1}, %2;" : "=f"(v.x), "=f"(v.y) : "l"(d)); return v; }

// smem layout (float units)
#define OFF_PHI  0          // 4096 uint2 = 8192 floats
#define OFF_PART 8192       // 2048 u64 = 4096 floats
#define OFF_XST  12288      // 256
#define OFF_HST  12544      // 256
#define OFF_LN1  12800      // 512
#define OFF_H1S  13312      // 512
#define OFF_LN2  13824      // 512
#define OFF_WSMU 14336      // 16 u64 = 32 floats
#define OFF_WSQU 14368      // 32
#define SM_FLOATS 14400
#define SMEM_BYTES (SM_FLOATS * 4)

#define DECL_ACC u64 A00 = 0, A01 = 0, A10 = 0, A11 = 0;

// FMA body for one j-pair given wa = (w[i0],w[i1]) at j, wb at j+1
#define PAIR_BODY(ACT, JP) {                                            \
    ulonglong2 aA = *(const ulonglong2*)&(ACT)[(2*(JP)) * 4];           \
    ulonglong2 aB = *(const ulonglong2*)&(ACT)[(2*(JP)+1) * 4];         \
    u64 w0 = bcast2(wa.x), w1 = bcast2(wa.y);                           \
    A00 = fma2(w0, aA.x, A00); A01 = fma2(w0, aA.y, A01);               \
    A10 = fma2(w1, aA.x, A10); A11 = fma2(w1, aA.y, A11);               \
    w0 = bcast2(wb.x); w1 = bcast2(wb.y);                               \
    A00 = fma2(w0, aB.x, A00); A01 = fma2(w0, aB.y, A01);               \
    A10 = fma2(w1, aB.x, A10); A11 = fma2(w1, aB.y, A11); }

#define WPAIR(WP_, ACT, JP) {                                           \
    uint2 wu = WP_[(JP) * 64 + i2];                                     \
    float2 wa = __half22float2(*(__half2*)&wu.x);                       \
    float2 wb = __half22float2(*(__half2*)&wu.y);                       \
    PAIR_BODY(ACT, JP) }

#define PPAIR(WP_, ACT, JP) {                                           \
    uint2 wu = WP_[(JP) * 64 + i2];                                     \
    uint2 pu = phiP[(JP) * 64 + i2];                                    \
    __half2 m0 = __hmul2(*(__half2*)&wu.x, *(__half2*)&pu.x);           \
    __half2 m1 = __hmul2(*(__half2*)&wu.y, *(__half2*)&pu.y);           \
    float2 wa = __half22float2(m0);                                     \
    float2 wb = __half22float2(m1);                                     \
    PAIR_BODY(ACT, JP) }

// partials: [slice][c][i2] u64, c = (i&1)*2 + batch-pair
#define STOREP() {                                                      \
    partd[js8 * 256 +   0 + i2] = A00;                                  \
    partd[js8 * 256 +  64 + i2] = A01;                                  \
    partd[js8 * 256 + 128 + i2] = A10;                                  \
    partd[js8 * 256 + 192 + i2] = A11; }

__global__ __launch_bounds__(512, 2)
void hier_kernel(const int*   __restrict__ tokens,
                 const int*   __restrict__ positions,
                 const float* __restrict__ emb,
                 const float* __restrict__ g1, const float* __restrict__ b1,
                 const float* __restrict__ g2, const float* __restrict__ b2,
                 float*       __restrict__ out)
{
    extern __shared__ __align__(16) float sm[];
    uint2* phiP  = (uint2*)(sm + OFF_PHI);      // [jp*64 + i2]
    u64*   partd = (u64*)(sm + OFF_PART);
    float* xsT   = sm + OFF_XST;                // [j][4b]
    float* hsT   = sm + OFF_HST;
    float* ln1T  = sm + OFF_LN1;
    float* h1sT  = sm + OFF_H1S;
    float* ln2T  = sm + OFF_LN2;
    u64*   wsmU  = (u64*)(sm + OFF_WSMU);
    u64*   wsqU  = (u64*)(sm + OFF_WSQU);

    const int tid = threadIdx.x;
    const int s   = blockIdx.x;
    const float sf = (float)positions[s];

    // ---- build pair-packed fp16 phiD: 4096 uint2 over 512 threads ----
#pragma unroll
    for (int m = 0; m < 8; ++m) {
        int idx = m * 512 + tid;
        float4 rp = g_rpP[idx];
        uint2 pk;
        pk.x = packh2(pcos(sf, rp.x), pcos(sf, rp.y));
        pk.y = packh2(pcos(sf, rp.z), pcos(sf, rp.w));
        phiP[idx] = pk;
    }

    // ---- gather embeddings: xsT[j][b] ----
    if (tid < 256) {
        int b0 = tid >> 6, j0 = tid & 63;
        int tok = tokens[b0 * S_LEN + s];
        xsT[j0 * 4 + b0] = emb[tok * 64 + j0];
    }
    __syncthreads();

    // =====================================================================
    // Layer 0 (V=64): 64 i x 8 j-slices of 8 (as R10)
    // =====================================================================
    {
        const int i = tid & 63, sl = tid >> 6;
        u64 a01 = 0, a23 = 0;
#pragma unroll
        for (int jj = 0; jj < 8; ++jj) {
            int j = sl * 8 + jj;
            float pw = g_cPt[j * 64 + i] * pcos(sf, g_rpVt[j * 64 + i]);
            u64 p2 = bcast2(pw);
            ulonglong2 ad = *(const ulonglong2*)&xsT[j * 4];
            a01 = fma2(p2, ad.x, a01);
            a23 = fma2(p2, ad.y, a23);
        }
        ulonglong2 st; st.x = a01; st.y = a23;
        *(ulonglong2*)&partd[sl * 128 + i * 2] = st;
    }
    __syncthreads();
    if (tid < 128) {
        u64 v = 0;
#pragma unroll
        for (int sl = 0; sl < 8; ++sl) v = add2(v, partd[sl * 128 + tid]);
        *(u64*)&hsT[tid * 2] = v;   // hsT[i][4b]
    }
    __syncthreads();

    // D-stage mapping (R10 geometry): warp = (i-half, j-slice)
    const int w   = tid >> 5;
    const int js8 = w >> 1;                  // 0..7
    const int i2  = (w & 1) * 32 + (tid & 31); // i-pair 0..63
    // reduce mapping (tid<256): c = tid>>6 (ih*2+bp), i2r = tid&63
    const int rc  = tid >> 6;
    const int rbp = rc & 1;
    const int rii = 2 * (tid & 63) + (rc >> 1);

    // =====================================================================
    // t1 = M1 @ h : jp<32, 4 per slice
    // =====================================================================
    {
        DECL_ACC;
        const int jp0 = js8 * 4;
        WPAIR(g_M1p, hsT, jp0 + 0); WPAIR(g_M1p, hsT, jp0 + 1);
        WPAIR(g_M1p, hsT, jp0 + 2); WPAIR(g_M1p, hsT, jp0 + 3);
        STOREP();
    }
    __syncthreads();

    // ---- reduce t1 + LayerNorm 1 (value kept in register across sync) ----
    u64 vKeep = 0;
    if (tid < 256) {
        u64 v = 0;
#pragma unroll
        for (int sl = 0; sl < 8; ++sl) v = add2(v, partd[sl * 256 + tid]);
        vKeep = v;
        u64 sv = v, sq = mul2(v, v);
#pragma unroll
        for (int o = 1; o <= 16; o <<= 1) {
            sv = add2(sv, __shfl_xor_sync(0xffffffffu, sv, o));
            sq = add2(sq, __shfl_xor_sync(0xffffffffu, sq, o));
        }
        if ((tid & 31) == 0) { wsmU[tid >> 5] = sv; wsqU[tid >> 5] = sq; }
    }
    __syncthreads();
    if (tid < 256) {
        u64 smS = add2(add2(wsmU[rbp * 2], wsmU[rbp * 2 + 1]),
                       add2(wsmU[rbp * 2 + 4], wsmU[rbp * 2 + 5]));
        u64 sqS = add2(add2(wsqU[rbp * 2], wsqU[rbp * 2 + 1]),
                       add2(wsqU[rbp * 2 + 4], wsqU[rbp * 2 + 5]));
        u64 mean2 = mul2(smS, bcast2(0.0078125f));
        u64 ex2   = mul2(sqS, bcast2(0.0078125f));
        u64 nm    = mul2(mean2, bcast2(-1.f));
        u64 var2  = fma2(mean2, nm, ex2);
        float2 vf = d2f(add2(var2, bcast2(1e-5f)));
        u64 rstd2 = f2d(rsqrtf(vf.x), rsqrtf(vf.y));
        u64 cen   = add2(vKeep, nm);
        *(u64*)&ln1T[rii * 4 + rbp * 2] =
            fma2(bcast2(g1[rii]), mul2(cen, rstd2), bcast2(b1[rii]));
    }
    __syncthreads();

    // =====================================================================
    // h1 = posnk(ln1, P1, phi) + R1 @ h : 8 P-jp + 4 R-jp per slice
    // =====================================================================
    {
        DECL_ACC;
        const int jp0 = js8 * 8;
        PPAIR(g_P1p, ln1T, jp0 + 0); PPAIR(g_P1p, ln1T, jp0 + 1);
        PPAIR(g_P1p, ln1T, jp0 + 2); PPAIR(g_P1p, ln1T, jp0 + 3);
        PPAIR(g_P1p, ln1T, jp0 + 4); PPAIR(g_P1p, ln1T, jp0 + 5);
        PPAIR(g_P1p, ln1T, jp0 + 6); PPAIR(g_P1p, ln1T, jp0 + 7);
        const int jr0 = js8 * 4;
        WPAIR(g_R1p, hsT, jr0 + 0); WPAIR(g_R1p, hsT, jr0 + 1);
        WPAIR(g_R1p, hsT, jr0 + 2); WPAIR(g_R1p, hsT, jr0 + 3);
        STOREP();
    }
    __syncthreads();
    if (tid < 256) {
        u64 v = 0;
#pragma unroll
        for (int sl = 0; sl < 8; ++sl) v = add2(v, partd[sl * 256 + tid]);
        *(u64*)&h1sT[rii * 4 + rbp * 2] = v;
    }
    __syncthreads();

    // =====================================================================
    // t2 = M2 @ h1 : 8 jp per slice
    // =====================================================================
    {
        DECL_ACC;
        const int jp0 = js8 * 8;
        WPAIR(g_M2p, h1sT, jp0 + 0); WPAIR(g_M2p, h1sT, jp0 + 1);
        WPAIR(g_M2p, h1sT, jp0 + 2); WPAIR(g_M2p, h1sT, jp0 + 3);
        WPAIR(g_M2p, h1sT, jp0 + 4); WPAIR(g_M2p, h1sT, jp0 + 5);
        WPAIR(g_M2p, h1sT, jp0 + 6); WPAIR(g_M2p, h1sT, jp0 + 7);
        STOREP();
    }
    __syncthreads();

    // ---- reduce t2 + LayerNorm 2 (t2d kept in register for residual) ----
    u64 t2d = 0;
    if (tid < 256) {
#pragma unroll
        for (int sl = 0; sl < 8; ++sl) t2d = add2(t2d, partd[sl * 256 + tid]);
        u64 sv = t2d, sq = mul2(t2d, t2d);
#pragma unroll
        for (int o = 1; o <= 16; o <<= 1) {
            sv = add2(sv, __shfl_xor_sync(0xffffffffu, sv, o));
            sq = add2(sq, __shfl_xor_sync(0xffffffffu, sq, o));
        }
        if ((tid & 31) == 0) { wsmU[tid >> 5] = sv; wsqU[tid >> 5] = sq; }
    }
    __syncthreads();
    if (tid < 256) {
        u64 smS = add2(add2(wsmU[rbp * 2], wsmU[rbp * 2 + 1]),
                       add2(wsmU[rbp * 2 + 4], wsmU[rbp * 2 + 5]));
        u64 sqS = add2(add2(wsqU[rbp * 2], wsqU[rbp * 2 + 1]),
                       add2(wsqU[rbp * 2 + 4], wsqU[rbp * 2 + 5]));
        u64 mean2 = mul2(smS, bcast2(0.0078125f));
        u64 ex2   = mul2(sqS, bcast2(0.0078125f));
        u64 nm    = mul2(mean2, bcast2(-1.f));
        u64 var2  = fma2(mean2, nm, ex2);
        float2 vf = d2f(add2(var2, bcast2(1e-5f)));
        u64 rstd2 = f2d(rsqrtf(vf.x), rsqrtf(vf.y));
        u64 cen   = add2(t2d, nm);
        *(u64*)&ln2T[rii * 4 + rbp * 2] =
            fma2(bcast2(g2[rii]), mul2(cen, rstd2), bcast2(b2[rii]));
    }
    __syncthreads();

    // =====================================================================
    // out = posnk(ln2, P2, phi) + t2
    // =====================================================================
    {
        DECL_ACC;
        const int jp0 = js8 * 8;
        PPAIR(g_P2p, ln2T, jp0 + 0); PPAIR(g_P2p, ln2T, jp0 + 1);
        PPAIR(g_P2p, ln2T, jp0 + 2); PPAIR(g_P2p, ln2T, jp0 + 3);
        PPAIR(g_P2p, ln2T, jp0 + 4); PPAIR(g_P2p, ln2T, jp0 + 5);
        PPAIR(g_P2p, ln2T, jp0 + 6); PPAIR(g_P2p, ln2T, jp0 + 7);
        STOREP();
    }
    __syncthreads();
    if (tid < 256) {
        u64 v = t2d;
#pragma unroll
        for (int sl = 0; sl < 8; ++sl) v = add2(v, partd[sl * 256 + tid]);
        float2 f = d2f(v);
        out[((size_t)(2 * rbp)     * S_LEN + s) * 128 + rii] = f.x;
        out[((size_t)(2 * rbp + 1) * S_LEN + s) * 128 + rii] = f.y;
    }
}

extern "C" void kernel_launch(void* const* d_in, const int* in_sizes, int n_in,
                              void* d_out, int out_size)
{
    const int*   tokens    = (const int*)  d_in[0];
    const int*   positions = (const int*)  d_in[1];
    const float* emb       = (const float*)d_in[2];
    const float* char_P    = (const float*)d_in[3];
    const float* M1        = (const float*)d_in[4];
    const float* P1        = (const float*)d_in[5];
    const float* g1        = (const float*)d_in[6];
    const float* b1        = (const float*)d_in[7];
    const float* R1        = (const float*)d_in[8];
    const float* M2        = (const float*)d_in[9];
    const float* P2        = (const float*)d_in[10];
    const float* g2        = (const float*)d_in[11];
    const float* b2        = (const float*)d_in[12];
    float* out = (float*)d_out;

    cudaFuncSetAttribute(hier_kernel,
                         cudaFuncAttributeMaxDynamicSharedMemorySize, SMEM_BYTES);

    prep_kernel<<<32, 512>>>(char_P, M1, R1, M2, P1, P2);
    hier_kernel<<<S_LEN, 512, SMEM_BYTES>>>(tokens, positions, emb,
                                            g1, b1, g2, b2, out);
}